// round 5
// baseline (speedup 1.0000x reference)
#include <cuda_runtime.h>
#include <math.h>

// Problem constants
#define GROUPS 4
#define NNODE  4096
#define KDIM   128
#define TILE   128
#define SSTRIDE 132   // padded row stride (floats): multiple of 4 (LDS.128 align), %32=4 (bank shift)

#define SMEM_BYTES (2 * KDIM * SSTRIDE * sizeof(float))  // 135168 B

__global__ __launch_bounds__(256, 1)
void bridge_sgemm_kernel(const float* __restrict__ nodes, float* __restrict__ out)
{
    const int g    = blockIdx.z;
    const int row0 = blockIdx.y * TILE;
    const int col0 = blockIdx.x * TILE;

    const float* __restrict__ A = nodes + (size_t)g * NNODE * KDIM;
    float* __restrict__ C       = out   + (size_t)g * NNODE * (size_t)NNODE;

    extern __shared__ float smem[];
    float* As = smem;                    // [KDIM][SSTRIDE]  (k-major, transposed from gmem)
    float* Bs = smem + KDIM * SSTRIDE;   // same layout

    const int tid = threadIdx.x;

    // ---- Load both 128x128 fp32 tiles, transposing [m][k] -> [k][m] in smem ----
    // 256 threads: m = tid>>1 (0..127), k-half = (tid&1)*64; 16 x float4 along k each.
    {
        const int m  = tid >> 1;
        const int kb = (tid & 1) * 64;
        const float4* arow = (const float4*)(A + (size_t)(row0 + m) * KDIM + kb);
        const float4* brow = (const float4*)(A + (size_t)(col0 + m) * KDIM + kb);
        #pragma unroll
        for (int i = 0; i < 16; i++) {
            const float4 av = arow[i];
            const float4 bv = brow[i];
            const int k = kb + 4 * i;
            As[(k + 0) * SSTRIDE + m] = av.x;
            As[(k + 1) * SSTRIDE + m] = av.y;
            As[(k + 2) * SSTRIDE + m] = av.z;
            As[(k + 3) * SSTRIDE + m] = av.w;
            Bs[(k + 0) * SSTRIDE + m] = bv.x;
            Bs[(k + 1) * SSTRIDE + m] = bv.y;
            Bs[(k + 2) * SSTRIDE + m] = bv.z;
            Bs[(k + 3) * SSTRIDE + m] = bv.w;
        }
    }
    __syncthreads();

    // ---- 8x8 register tile per thread; 16x16 thread grid over the 128x128 tile ----
    const int tx = tid & 15;   // column group
    const int ty = tid >> 4;   // row group

    float acc[8][8];
    #pragma unroll
    for (int i = 0; i < 8; i++)
        #pragma unroll
        for (int j = 0; j < 8; j++)
            acc[i][j] = 0.0f;

    const float* ap = As + ty * 8;
    const float* bp = Bs + tx * 8;

    #pragma unroll 4
    for (int k = 0; k < KDIM; k++, ap += SSTRIDE, bp += SSTRIDE) {
        float a[8], b[8];
        const float4 a0 = *(const float4*)(ap);
        const float4 a1 = *(const float4*)(ap + 4);
        const float4 b0 = *(const float4*)(bp);
        const float4 b1 = *(const float4*)(bp + 4);
        a[0]=a0.x; a[1]=a0.y; a[2]=a0.z; a[3]=a0.w;
        a[4]=a1.x; a[5]=a1.y; a[6]=a1.z; a[7]=a1.w;
        b[0]=b0.x; b[1]=b0.y; b[2]=b0.z; b[3]=b0.w;
        b[4]=b1.x; b[5]=b1.y; b[6]=b1.z; b[7]=b1.w;

        #pragma unroll
        for (int i = 0; i < 8; i++)
            #pragma unroll
            for (int j = 0; j < 8; j++)
                acc[i][j] = fmaf(a[i], b[j], acc[i][j]);
    }

    // ---- Epilogue: sigmoid + threshold, vectorized stores ----
    const int   crow = row0 + ty * 8;
    const int   ccol = col0 + tx * 8;
    float* __restrict__ Cbase = C + (size_t)crow * NNODE + ccol;

    #pragma unroll
    for (int i = 0; i < 8; i++) {
        float v[8];
        #pragma unroll
        for (int j = 0; j < 8; j++) {
            const float x = acc[i][j];
            // accurate sigmoid (expf, not __expf): threshold flips are the
            // dominant error mode, keep the band as narrow as possible
            const float s = 1.0f / (1.0f + expf(-x));
            v[j] = (s < 0.6f) ? 0.0f : s;
        }
        float4* dst = (float4*)(Cbase + (size_t)i * NNODE);
        dst[0] = make_float4(v[0], v[1], v[2], v[3]);
        dst[1] = make_float4(v[4], v[5], v[6], v[7]);
    }
}

extern "C" void kernel_launch(void* const* d_in, const int* in_sizes, int n_in,
                              void* d_out, int out_size)
{
    (void)in_sizes; (void)n_in; (void)out_size;
    const float* nodes = (const float*)d_in[0];
    float* out = (float*)d_out;

    static int smem_configured = 0;
    if (!smem_configured) {
        cudaError_t e = cudaFuncSetAttribute(bridge_sgemm_kernel,
                                             cudaFuncAttributeMaxDynamicSharedMemorySize,
                                             (int)SMEM_BYTES);
        if (e == cudaSuccess) smem_configured = 1;
    }

    dim3 grid(NNODE / TILE, NNODE / TILE, GROUPS);  // 32 x 32 x 4
    bridge_sgemm_kernel<<<grid, 256, SMEM_BYTES>>>(nodes, out);
}

// round 6
// speedup vs baseline: 1.5730x; 1.5730x over previous
#include <cuda_runtime.h>
#include <math.h>

// Problem constants
#define GROUPS 4
#define NNODE  4096
#define KDIM   128
#define TILE   128
#define NB     (NNODE / TILE)            // 32 block-rows
#define NPAIRS (NB * (NB + 1) / 2)       // 528 upper-triangle block pairs
#define SSTRIDE 132                      // padded smem row stride (floats)

#define SMEM_BYTES (2 * KDIM * SSTRIDE * sizeof(float))   // 135168 B

typedef unsigned long long u64;

// ---- f32x2 packed-math helpers (sm_103a; ptxas won't auto-fuse these) ----
__device__ __forceinline__ u64 pack_dup(float a) {
    u64 r; asm("mov.b64 %0, {%1, %1};" : "=l"(r) : "f"(a)); return r;
}
__device__ __forceinline__ void ffma2(u64 &d, u64 a, u64 b) {
    asm("fma.rn.f32x2 %0, %1, %2, %3;" : "=l"(d) : "l"(a), "l"(b), "l"(d));
}
__device__ __forceinline__ float2 unpack2(u64 v) {
    float2 r; asm("mov.b64 {%0, %1}, %2;" : "=f"(r.x), "=f"(r.y) : "l"(v)); return r;
}

__global__ __launch_bounds__(256, 1)
void bridge_sgemm_kernel(const float* __restrict__ nodes, float* __restrict__ out)
{
    // ---- map blockIdx.x -> upper-triangle block pair (bi <= bj) ----
    const int t = blockIdx.x;
    // start(bi) = bi*NB - bi*(bi-1)/2 ; row bi holds NB-bi pairs
    int bi = (int)((float)NB + 0.5f - sqrtf(((float)NB + 0.5f) * ((float)NB + 0.5f) - 2.0f * (float)t));
    if (bi < 0) bi = 0;
    if (bi >= NB) bi = NB - 1;
    while (bi + 1 <= NB - 1 && ((bi + 1) * NB - (bi + 1) * bi / 2) <= t) bi++;
    while (bi > 0 && (bi * NB - bi * (bi - 1) / 2) > t) bi--;
    const int bj = bi + (t - (bi * NB - bi * (bi - 1) / 2));

    const int g    = blockIdx.y;
    const int row0 = bi * TILE;
    const int col0 = bj * TILE;
    const bool mirror = (bi != bj);

    const float* __restrict__ A = nodes + (size_t)g * NNODE * KDIM;
    float* __restrict__ C       = out   + (size_t)g * NNODE * (size_t)NNODE;

    extern __shared__ float smem[];
    float* As = smem;                    // [KDIM][SSTRIDE]  k-major (transposed)
    float* Bs = smem + KDIM * SSTRIDE;

    const int tid = threadIdx.x;

    // ---- load both 128x128 fp32 tiles, transposing [m][k] -> [k][m] ----
    {
        const int m  = tid >> 1;
        const int kb = (tid & 1) * 64;
        const float4* arow = (const float4*)(A + (size_t)(row0 + m) * KDIM + kb);
        const float4* brow = (const float4*)(A + (size_t)(col0 + m) * KDIM + kb);
        #pragma unroll
        for (int i = 0; i < 16; i++) {
            const float4 av = arow[i];
            const float4 bv = brow[i];
            const int k = kb + 4 * i;
            As[(k + 0) * SSTRIDE + m] = av.x;
            As[(k + 1) * SSTRIDE + m] = av.y;
            As[(k + 2) * SSTRIDE + m] = av.z;
            As[(k + 3) * SSTRIDE + m] = av.w;
            Bs[(k + 0) * SSTRIDE + m] = bv.x;
            Bs[(k + 1) * SSTRIDE + m] = bv.y;
            Bs[(k + 2) * SSTRIDE + m] = bv.z;
            Bs[(k + 3) * SSTRIDE + m] = bv.w;
        }
    }
    __syncthreads();

    // ---- 8x8 per-thread tile, accumulators packed as f32x2 pairs along j ----
    const int tx = tid & 15;
    const int ty = tid >> 4;

    u64 acc[8][4];
    #pragma unroll
    for (int i = 0; i < 8; i++)
        #pragma unroll
        for (int j = 0; j < 4; j++)
            acc[i][j] = 0ull;

    const float* ap = As + ty * 8;
    const float* bp = Bs + tx * 8;

    #pragma unroll 2
    for (int k = 0; k < KDIM; k++, ap += SSTRIDE, bp += SSTRIDE) {
        // b pairs come straight out of LDS.128 as aligned 64-bit halves (no packing)
        const ulonglong2 b01 = *(const ulonglong2*)(bp);      // {(b0,b1),(b2,b3)}
        const ulonglong2 b23 = *(const ulonglong2*)(bp + 4);  // {(b4,b5),(b6,b7)}
        u64 bb[4];
        bb[0] = b01.x; bb[1] = b01.y; bb[2] = b23.x; bb[3] = b23.y;

        const float4 a0 = *(const float4*)(ap);
        const float4 a1 = *(const float4*)(ap + 4);
        u64 aa[8];
        aa[0] = pack_dup(a0.x); aa[1] = pack_dup(a0.y);
        aa[2] = pack_dup(a0.z); aa[3] = pack_dup(a0.w);
        aa[4] = pack_dup(a1.x); aa[5] = pack_dup(a1.y);
        aa[6] = pack_dup(a1.z); aa[7] = pack_dup(a1.w);

        #pragma unroll
        for (int i = 0; i < 8; i++)
            #pragma unroll
            for (int j = 0; j < 4; j++)
                ffma2(acc[i][j], aa[i], bb[j]);
    }

    // ---- epilogue: sigmoid + threshold ----
    float v[8][8];
    #pragma unroll
    for (int i = 0; i < 8; i++) {
        #pragma unroll
        for (int j = 0; j < 4; j++) {
            const float2 p = unpack2(acc[i][j]);
            // accurate expf: threshold flips are the dominant error mode
            const float s0 = 1.0f / (1.0f + expf(-p.x));
            const float s1 = 1.0f / (1.0f + expf(-p.y));
            v[i][2 * j]     = (s0 < 0.6f) ? 0.0f : s0;
            v[i][2 * j + 1] = (s1 < 0.6f) ? 0.0f : s1;
        }
    }

    // normal tile: rows row0+ty*8+i, cols col0+tx*8+j
    {
        float* __restrict__ Cbase = C + (size_t)(row0 + ty * 8) * NNODE + (col0 + tx * 8);
        #pragma unroll
        for (int i = 0; i < 8; i++) {
            float4* dst = (float4*)(Cbase + (size_t)i * NNODE);
            dst[0] = make_float4(v[i][0], v[i][1], v[i][2], v[i][3]);
            dst[1] = make_float4(v[i][4], v[i][5], v[i][6], v[i][7]);
        }
    }

    // mirrored tile (C = C^T exactly: same multiply pairs, same k order)
    if (mirror) {
        float* __restrict__ Mbase = C + (size_t)(col0 + tx * 8) * NNODE + (row0 + ty * 8);
        #pragma unroll
        for (int j = 0; j < 8; j++) {
            float4* dst = (float4*)(Mbase + (size_t)j * NNODE);
            dst[0] = make_float4(v[0][j], v[1][j], v[2][j], v[3][j]);
            dst[1] = make_float4(v[4][j], v[5][j], v[6][j], v[7][j]);
        }
    }
}

extern "C" void kernel_launch(void* const* d_in, const int* in_sizes, int n_in,
                              void* d_out, int out_size)
{
    (void)in_sizes; (void)n_in; (void)out_size;
    const float* nodes = (const float*)d_in[0];
    float* out = (float*)d_out;

    static int smem_configured = 0;
    if (!smem_configured) {
        cudaError_t e = cudaFuncSetAttribute(bridge_sgemm_kernel,
                                             cudaFuncAttributeMaxDynamicSharedMemorySize,
                                             (int)SMEM_BYTES);
        if (e == cudaSuccess) smem_configured = 1;
    }

    dim3 grid(NPAIRS, GROUPS);   // 528 block-pairs x 4 groups = 2112 CTAs
    bridge_sgemm_kernel<<<grid, 256, SMEM_BYTES>>>(nodes, out);
}